// round 4
// baseline (speedup 1.0000x reference)
#include <cuda_runtime.h>
#include <cstdint>

#define N_NODES 100000
#define N_EDGES 1600000

// ---------------- scratch (no allocations allowed) ----------------
__device__ float g_y[(size_t)N_NODES * 128];   // transformed features [yl | yr]
__device__ float g_agg[(size_t)N_NODES * 64];  // scatter accumulator
__device__ float g_h[(size_t)N_NODES * 64];    // layer activations
__device__ float g_deg[N_NODES];
__device__ float g_dinv[N_NODES];

// ---------------- utility kernels ----------------
__global__ void k_zero(float* __restrict__ p, int n4) {
    int i = blockIdx.x * blockDim.x + threadIdx.x;
    if (i < n4) ((float4*)p)[i] = make_float4(0.f, 0.f, 0.f, 0.f);
}

__global__ void k_deg(const int* __restrict__ ei, float* __restrict__ deg) {
    int i = blockIdx.x * blockDim.x + threadIdx.x;
    if (i < N_EDGES) {
        int dst = ei[N_EDGES + i];
        atomicAdd(deg + dst, 1.0f);
    }
}

__global__ void k_dinv(const float* __restrict__ deg, float* __restrict__ dinv) {
    int i = blockIdx.x * blockDim.x + threadIdx.x;
    if (i < N_NODES) dinv[i] = 1.0f / fmaxf(deg[i], 1.0f);
}

// ---------------- GEMM: C[N,NOUT] = A[N,64] @ [Wl | Wr] ----------------
// Block tile: 64 rows x NOUT cols, K=64 (full). 256 threads.
// Thread tile: 8 rows x (NOUT/32) cols. smem rows padded to 68 floats
// (17 x 16B -> odd 16B stride, conflict-free float4 access).
template <int NOUT>
__global__ __launch_bounds__(256) void k_gemm(
    const float* __restrict__ A, const float* __restrict__ Wl,
    const float* __restrict__ Wr, float* __restrict__ C) {
    constexpr int FOUT = NOUT / 2;
    constexpr int NT = NOUT / 32;
    extern __shared__ float sm[];
    float* As = sm;             // [64][68]
    float* Bt = sm + 64 * 68;   // [NOUT][68], Bt[col][k] = B[k][col]

    const int tid = threadIdx.x;
    const int base = blockIdx.x * 64;

    // load A tile (row-major, contiguous -> float4 loads)
#pragma unroll
    for (int i = 0; i < 4; i++) {
        int lin = tid + i * 256;      // float4 id: 0..1023
        int row = lin >> 4;
        int k4 = lin & 15;
        float4 v = make_float4(0.f, 0.f, 0.f, 0.f);
        if (base + row < N_NODES)
            v = *(const float4*)(A + (size_t)(base + row) * 64 + k4 * 4);
        *(float4*)(As + row * 68 + k4 * 4) = v;
    }
    // load B transposed
#pragma unroll
    for (int i = 0; i < (NOUT * 64) / 256; i++) {
        int lin = tid + i * 256;
        int k = lin / NOUT;
        int col = lin % NOUT;
        float v = (col < FOUT) ? Wl[k * FOUT + col] : Wr[k * FOUT + (col - FOUT)];
        Bt[col * 68 + k] = v;
    }
    __syncthreads();

    const int tm = tid >> 5;  // 0..7 (same within a warp -> As broadcasts)
    const int tn = tid & 31;

    float acc[8][NT];
#pragma unroll
    for (int m = 0; m < 8; m++)
#pragma unroll
        for (int j = 0; j < NT; j++) acc[m][j] = 0.f;

#pragma unroll
    for (int k0 = 0; k0 < 64; k0 += 4) {
        float4 b4[NT];
#pragma unroll
        for (int j = 0; j < NT; j++)
            b4[j] = *(const float4*)(Bt + (tn + 32 * j) * 68 + k0);
#pragma unroll
        for (int m = 0; m < 8; m++) {
            float4 a4 = *(const float4*)(As + (tm * 8 + m) * 68 + k0);
#pragma unroll
            for (int j = 0; j < NT; j++) {
                acc[m][j] += a4.x * b4[j].x;
                acc[m][j] += a4.y * b4[j].y;
                acc[m][j] += a4.z * b4[j].z;
                acc[m][j] += a4.w * b4[j].w;
            }
        }
    }

#pragma unroll
    for (int m = 0; m < 8; m++) {
        int row = base + tm * 8 + m;
        if (row < N_NODES) {
#pragma unroll
            for (int j = 0; j < NT; j++)
                C[(size_t)row * NOUT + tn + 32 * j] = acc[m][j];
        }
    }
}

// ---------------- scatter: agg[dst] += Y[src, 0:F] ----------------
// F/4 threads per edge, each moves one float4 with red.global.add.v4.f32.
template <int F>
__global__ void k_scatter(const int* __restrict__ ei, const float* __restrict__ Y,
                          int ystride, float* __restrict__ agg) {
    constexpr int C = F / 4;
    long long t = (long long)blockIdx.x * blockDim.x + threadIdx.x;
    if (t >= (long long)N_EDGES * C) return;
    int e = (int)(t / C);
    int c = (int)(t % C);
    int src = __ldg(ei + e);
    int dst = __ldg(ei + N_EDGES + e);
    float4 v = *(const float4*)(Y + (size_t)src * ystride + c * 4);
    float* p = agg + (size_t)dst * F + c * 4;
    asm volatile("red.global.add.v4.f32 [%0], {%1,%2,%3,%4};"
                 :: "l"(p), "f"(v.x), "f"(v.y), "f"(v.z), "f"(v.w)
                 : "memory");
}

// ---------------- combine: out = agg*dinv + yr + b (optional ELU) ----------------
__global__ void k_combine(const float* __restrict__ agg, const float* __restrict__ Y,
                          int ystride, int off, const float* __restrict__ bias,
                          const float* __restrict__ dinv, float* __restrict__ out,
                          int F, int doElu) {
    int C = F / 4;
    int i = blockIdx.x * blockDim.x + threadIdx.x;
    if (i >= N_NODES * C) return;
    int n = i / C, c = i % C;
    float d = dinv[n];
    float4 a = *(const float4*)(agg + (size_t)n * F + c * 4);
    float4 r = *(const float4*)(Y + (size_t)n * ystride + off + c * 4);
    float4 bb = *(const float4*)(bias + c * 4);
    float4 o;
    o.x = a.x * d + r.x + bb.x;
    o.y = a.y * d + r.y + bb.y;
    o.z = a.z * d + r.z + bb.z;
    o.w = a.w * d + r.w + bb.w;
    if (doElu) {
        o.x = o.x > 0.f ? o.x : (__expf(o.x) - 1.f);
        o.y = o.y > 0.f ? o.y : (__expf(o.y) - 1.f);
        o.z = o.z > 0.f ? o.z : (__expf(o.z) - 1.f);
        o.w = o.w > 0.f ? o.w : (__expf(o.w) - 1.f);
    }
    *(float4*)(out + (size_t)n * F + c * 4) = o;
}

// ---------------- host ----------------
extern "C" void kernel_launch(void* const* d_in, const int* in_sizes, int n_in,
                              void* d_out, int out_size) {
    const float* x   = (const float*)d_in[0];
    const int*   ei  = (const int*)d_in[1];
    const float* Wl0 = (const float*)d_in[2];
    const float* Wr0 = (const float*)d_in[3];
    const float* b0  = (const float*)d_in[4];
    const float* Wl1 = (const float*)d_in[5];
    const float* Wr1 = (const float*)d_in[6];
    const float* b1  = (const float*)d_in[7];
    const float* Wl2 = (const float*)d_in[8];
    const float* Wr2 = (const float*)d_in[9];
    const float* b2  = (const float*)d_in[10];
    float* out = (float*)d_out;

    float *y, *agg, *h, *deg, *dinv;
    cudaGetSymbolAddress((void**)&y, g_y);
    cudaGetSymbolAddress((void**)&agg, g_agg);
    cudaGetSymbolAddress((void**)&h, g_h);
    cudaGetSymbolAddress((void**)&deg, g_deg);
    cudaGetSymbolAddress((void**)&dinv, g_dinv);

    const int smem128 = (64 * 68 + 128 * 68) * 4;
    const int smem64  = (64 * 68 + 64 * 68) * 4;
    cudaFuncSetAttribute(k_gemm<128>, cudaFuncAttributeMaxDynamicSharedMemorySize, smem128);
    cudaFuncSetAttribute(k_gemm<64>,  cudaFuncAttributeMaxDynamicSharedMemorySize, smem64);

    const int gemmGrid = (N_NODES + 63) / 64;

    // degrees (recomputed every call; deterministic work)
    k_zero<<<(N_NODES / 4 + 255) / 256, 256>>>(deg, N_NODES / 4);
    k_deg<<<(N_EDGES + 255) / 256, 256>>>(ei, deg);
    k_dinv<<<(N_NODES + 255) / 256, 256>>>(deg, dinv);

    // ---- layer 0: x -> h (64) ----
    k_gemm<128><<<gemmGrid, 256, smem128>>>(x, Wl0, Wr0, y);
    k_zero<<<(N_NODES * 16 + 255) / 256, 256>>>(agg, N_NODES * 16);
    k_scatter<64><<<(int)(((long long)N_EDGES * 16 + 255) / 256), 256>>>(ei, y, 128, agg);
    k_combine<<<(N_NODES * 16 + 255) / 256, 256>>>(agg, y, 128, 64, b0, dinv, h, 64, 1);

    // ---- layer 1: h -> h (64) ----
    k_gemm<128><<<gemmGrid, 256, smem128>>>(h, Wl1, Wr1, y);
    k_zero<<<(N_NODES * 16 + 255) / 256, 256>>>(agg, N_NODES * 16);
    k_scatter<64><<<(int)(((long long)N_EDGES * 16 + 255) / 256), 256>>>(ei, y, 128, agg);
    k_combine<<<(N_NODES * 16 + 255) / 256, 256>>>(agg, y, 128, 64, b1, dinv, h, 64, 1);

    // ---- layer 2: h -> out (32, no activation) ----
    k_gemm<64><<<gemmGrid, 256, smem64>>>(h, Wl2, Wr2, y);
    k_zero<<<(N_NODES * 8 + 255) / 256, 256>>>(agg, N_NODES * 8);
    k_scatter<32><<<(int)(((long long)N_EDGES * 8 + 255) / 256), 256>>>(ei, y, 64, agg);
    k_combine<<<(N_NODES * 8 + 255) / 256, 256>>>(agg, y, 64, 32, b2, dinv, out, 32, 0);
}

// round 6
// speedup vs baseline: 1.5017x; 1.5017x over previous
#include <cuda_runtime.h>
#include <cstdint>

#define N_NODES 100000
#define N_EDGES 1600000
#define NB 98  // ceil(N_NODES / 1024)

// ---------------- scratch (no allocations allowed) ----------------
__device__ float g_y[(size_t)N_NODES * 128];   // transformed features [yl | yr]
__device__ float g_h[(size_t)N_NODES * 64];    // layer activations
__device__ int   g_deg[N_NODES];
__device__ int   g_rowp[N_NODES];
__device__ int   g_cursor[N_NODES];
__device__ int   g_csr[N_EDGES];               // src ids grouped by dst
__device__ int   g_bsum[128];
__device__ int   g_boff[128];

// ---------------- CSR build ----------------
__global__ void k_zero_int(int* __restrict__ p, int n) {
    int i = blockIdx.x * blockDim.x + threadIdx.x;
    if (i < n) p[i] = 0;
}

__global__ void k_hist(const int* __restrict__ ei, int* __restrict__ deg) {
    int i = blockIdx.x * blockDim.x + threadIdx.x;
    if (i < N_EDGES) atomicAdd(deg + ei[N_EDGES + i], 1);
}

// block-local exclusive scan (1024 elems/block), emit block totals
__global__ __launch_bounds__(1024) void k_scan_local(
    const int* __restrict__ deg, int* __restrict__ rowp, int* __restrict__ bsum) {
    __shared__ int s[1024];
    int t = threadIdx.x;
    int i = blockIdx.x * 1024 + t;
    int v = (i < N_NODES) ? deg[i] : 0;
    s[t] = v;
    __syncthreads();
#pragma unroll
    for (int d = 1; d < 1024; d <<= 1) {
        int x = (t >= d) ? s[t - d] : 0;
        __syncthreads();
        s[t] += x;
        __syncthreads();
    }
    if (i < N_NODES) rowp[i] = s[t] - v;  // exclusive
    if (t == 1023) bsum[blockIdx.x] = s[1023];
}

__global__ void k_scan_bsum(const int* __restrict__ bsum, int* __restrict__ boff) {
    if (threadIdx.x == 0 && blockIdx.x == 0) {
        int run = 0;
        for (int b = 0; b < NB; b++) { boff[b] = run; run += bsum[b]; }
    }
}

__global__ void k_scan_add(int* __restrict__ rowp, const int* __restrict__ boff,
                           int* __restrict__ cursor) {
    int i = blockIdx.x * blockDim.x + threadIdx.x;
    if (i < N_NODES) {
        int r = rowp[i] + boff[i >> 10];
        rowp[i] = r;
        cursor[i] = r;
    }
}

__global__ void k_fill(const int* __restrict__ ei, int* __restrict__ cursor,
                       int* __restrict__ csr) {
    int i = blockIdx.x * blockDim.x + threadIdx.x;
    if (i < N_EDGES) {
        int src = ei[i];
        int dst = ei[N_EDGES + i];
        int pos = atomicAdd(cursor + dst, 1);
        csr[pos] = src;
    }
}

// ---------------- GEMM: C[N,NOUT] = A[N,64] @ [Wl | Wr] ----------------
template <int NOUT>
__global__ __launch_bounds__(256) void k_gemm(
    const float* __restrict__ A, const float* __restrict__ Wl,
    const float* __restrict__ Wr, float* __restrict__ C) {
    constexpr int FOUT = NOUT / 2;
    constexpr int NT = NOUT / 32;
    extern __shared__ float sm[];
    float* As = sm;             // [64][68]
    float* Bt = sm + 64 * 68;   // [NOUT][68], Bt[col][k] = B[k][col]

    const int tid = threadIdx.x;
    const int base = blockIdx.x * 64;

#pragma unroll
    for (int i = 0; i < 4; i++) {
        int lin = tid + i * 256;
        int row = lin >> 4;
        int k4 = lin & 15;
        float4 v = make_float4(0.f, 0.f, 0.f, 0.f);
        if (base + row < N_NODES)
            v = *(const float4*)(A + (size_t)(base + row) * 64 + k4 * 4);
        *(float4*)(As + row * 68 + k4 * 4) = v;
    }
#pragma unroll
    for (int i = 0; i < (NOUT * 64) / 256; i++) {
        int lin = tid + i * 256;
        int k = lin / NOUT;
        int col = lin % NOUT;
        float v = (col < FOUT) ? Wl[k * FOUT + col] : Wr[k * FOUT + (col - FOUT)];
        Bt[col * 68 + k] = v;
    }
    __syncthreads();

    const int tm = tid >> 5;
    const int tn = tid & 31;

    float acc[8][NT];
#pragma unroll
    for (int m = 0; m < 8; m++)
#pragma unroll
        for (int j = 0; j < NT; j++) acc[m][j] = 0.f;

#pragma unroll
    for (int k0 = 0; k0 < 64; k0 += 4) {
        float4 b4[NT];
#pragma unroll
        for (int j = 0; j < NT; j++)
            b4[j] = *(const float4*)(Bt + (tn + 32 * j) * 68 + k0);
#pragma unroll
        for (int m = 0; m < 8; m++) {
            float4 a4 = *(const float4*)(As + (tm * 8 + m) * 68 + k0);
#pragma unroll
            for (int j = 0; j < NT; j++) {
                acc[m][j] += a4.x * b4[j].x;
                acc[m][j] += a4.y * b4[j].y;
                acc[m][j] += a4.z * b4[j].z;
                acc[m][j] += a4.w * b4[j].w;
            }
        }
    }

#pragma unroll
    for (int m = 0; m < 8; m++) {
        int row = base + tm * 8 + m;
        if (row < N_NODES) {
#pragma unroll
            for (int j = 0; j < NT; j++)
                C[(size_t)row * NOUT + tn + 32 * j] = acc[m][j];
        }
    }
}

// ---------------- fused aggregate+combine, F=64 (one warp per node) ----------------
// out[n] = elu?( mean_{s in nbr(n)} yl[s] + yr[n] + b )
__global__ __launch_bounds__(256) void k_agg64(
    const int* __restrict__ rowp, const int* __restrict__ deg,
    const int* __restrict__ csr, const float* __restrict__ Y,
    const float* __restrict__ bias, float* __restrict__ out, int doElu) {
    int warp = (blockIdx.x * blockDim.x + threadIdx.x) >> 5;
    int lane = threadIdx.x & 31;
    if (warp >= N_NODES) return;
    int start = rowp[warp];
    int cnt = deg[warp];
    const float* Ycol = Y + lane * 2;

    float ax = 0.f, ay = 0.f;
    int j = 0;
    for (; j + 4 <= cnt; j += 4) {
        int s0 = __ldg(csr + start + j + 0);
        int s1 = __ldg(csr + start + j + 1);
        int s2 = __ldg(csr + start + j + 2);
        int s3 = __ldg(csr + start + j + 3);
        float2 v0 = *(const float2*)(Ycol + (size_t)s0 * 128);
        float2 v1 = *(const float2*)(Ycol + (size_t)s1 * 128);
        float2 v2 = *(const float2*)(Ycol + (size_t)s2 * 128);
        float2 v3 = *(const float2*)(Ycol + (size_t)s3 * 128);
        ax += v0.x; ay += v0.y;
        ax += v1.x; ay += v1.y;
        ax += v2.x; ay += v2.y;
        ax += v3.x; ay += v3.y;
    }
    for (; j < cnt; j++) {
        int s = __ldg(csr + start + j);
        float2 v = *(const float2*)(Ycol + (size_t)s * 128);
        ax += v.x; ay += v.y;
    }

    float dinv = 1.0f / fmaxf((float)cnt, 1.0f);
    float2 r = *(const float2*)(Y + (size_t)warp * 128 + 64 + lane * 2);
    float2 bb = *(const float2*)(bias + lane * 2);
    float ox = ax * dinv + r.x + bb.x;
    float oy = ay * dinv + r.y + bb.y;
    if (doElu) {
        ox = ox > 0.f ? ox : (__expf(ox) - 1.f);
        oy = oy > 0.f ? oy : (__expf(oy) - 1.f);
    }
    *(float2*)(out + (size_t)warp * 64 + lane * 2) = make_float2(ox, oy);
}

// ---------------- fused aggregate+combine, F=32 (final layer, no ELU) --------------
__global__ __launch_bounds__(256) void k_agg32(
    const int* __restrict__ rowp, const int* __restrict__ deg,
    const int* __restrict__ csr, const float* __restrict__ Y,
    const float* __restrict__ bias, float* __restrict__ out) {
    int warp = (blockIdx.x * blockDim.x + threadIdx.x) >> 5;
    int lane = threadIdx.x & 31;
    if (warp >= N_NODES) return;
    int start = rowp[warp];
    int cnt = deg[warp];
    const float* Ycol = Y + lane;

    float ax = 0.f;
    int j = 0;
    for (; j + 4 <= cnt; j += 4) {
        int s0 = __ldg(csr + start + j + 0);
        int s1 = __ldg(csr + start + j + 1);
        int s2 = __ldg(csr + start + j + 2);
        int s3 = __ldg(csr + start + j + 3);
        float v0 = Ycol[(size_t)s0 * 64];
        float v1 = Ycol[(size_t)s1 * 64];
        float v2 = Ycol[(size_t)s2 * 64];
        float v3 = Ycol[(size_t)s3 * 64];
        ax += v0; ax += v1; ax += v2; ax += v3;
    }
    for (; j < cnt; j++) {
        int s = __ldg(csr + start + j);
        ax += Ycol[(size_t)s * 64];
    }

    float dinv = 1.0f / fmaxf((float)cnt, 1.0f);
    float r = Y[(size_t)warp * 64 + 32 + lane];
    float ox = ax * dinv + r + bias[lane];
    out[(size_t)warp * 32 + lane] = ox;
}

// ---------------- host ----------------
extern "C" void kernel_launch(void* const* d_in, const int* in_sizes, int n_in,
                              void* d_out, int out_size) {
    const float* x   = (const float*)d_in[0];
    const int*   ei  = (const int*)d_in[1];
    const float* Wl0 = (const float*)d_in[2];
    const float* Wr0 = (const float*)d_in[3];
    const float* b0  = (const float*)d_in[4];
    const float* Wl1 = (const float*)d_in[5];
    const float* Wr1 = (const float*)d_in[6];
    const float* b1  = (const float*)d_in[7];
    const float* Wl2 = (const float*)d_in[8];
    const float* Wr2 = (const float*)d_in[9];
    const float* b2  = (const float*)d_in[10];
    float* out = (float*)d_out;

    float *y, *h;
    int *deg, *rowp, *cursor, *csr, *bsum, *boff;
    cudaGetSymbolAddress((void**)&y, g_y);
    cudaGetSymbolAddress((void**)&h, g_h);
    cudaGetSymbolAddress((void**)&deg, g_deg);
    cudaGetSymbolAddress((void**)&rowp, g_rowp);
    cudaGetSymbolAddress((void**)&cursor, g_cursor);
    cudaGetSymbolAddress((void**)&csr, g_csr);
    cudaGetSymbolAddress((void**)&bsum, g_bsum);
    cudaGetSymbolAddress((void**)&boff, g_boff);

    const int smem128 = (64 * 68 + 128 * 68) * 4;
    const int smem64  = (64 * 68 + 64 * 68) * 4;
    cudaFuncSetAttribute(k_gemm<128>, cudaFuncAttributeMaxDynamicSharedMemorySize, smem128);
    cudaFuncSetAttribute(k_gemm<64>,  cudaFuncAttributeMaxDynamicSharedMemorySize, smem64);

    const int gemmGrid = (N_NODES + 63) / 64;
    const int aggGrid = (N_NODES * 32 + 255) / 256;  // one warp per node

    // ---- CSR build (every call; deterministic work) ----
    k_zero_int<<<(N_NODES + 255) / 256, 256>>>(deg, N_NODES);
    k_hist<<<(N_EDGES + 255) / 256, 256>>>(ei, deg);
    k_scan_local<<<NB, 1024>>>(deg, rowp, bsum);
    k_scan_bsum<<<1, 32>>>(bsum, boff);
    k_scan_add<<<(N_NODES + 255) / 256, 256>>>(rowp, boff, cursor);
    k_fill<<<(N_EDGES + 255) / 256, 256>>>(ei, cursor, csr);

    // ---- layer 0: x -> h (64) ----
    k_gemm<128><<<gemmGrid, 256, smem128>>>(x, Wl0, Wr0, y);
    k_agg64<<<aggGrid, 256>>>(rowp, deg, csr, y, b0, h, 1);

    // ---- layer 1: h -> h (64) ----
    k_gemm<128><<<gemmGrid, 256, smem128>>>(h, Wl1, Wr1, y);
    k_agg64<<<aggGrid, 256>>>(rowp, deg, csr, y, b1, h, 1);

    // ---- layer 2: h -> out (32, no activation) ----
    k_gemm<64><<<gemmGrid, 256, smem64>>>(h, Wl2, Wr2, y);
    k_agg32<<<aggGrid, 256>>>(rowp, deg, csr, y, b2, out);
}